// round 2
// baseline (speedup 1.0000x reference)
#include <cuda_runtime.h>
#include <math.h>

#define NM 64
#define NA 16384
#define HIDN 192
#define EMAX 524288
#define OFFS 0.0195141f
#define PREF (-138.935485f * (1.0f - 1.0f/78.5f))
#define SACONST (4.184f * 0.00542f * 100.0f)

__device__ float d_scaleS[NM], d_scaleE[NM];
__device__ int   d_gb_off[NA + 1], d_gnn_off[NA + 1];
__device__ float d_edge_d[EMAX];
__device__ float d_gd[EMAX];
__device__ float d_psiS[NA];
__device__ float d_Born[NA], d_dBdS[NA];
__device__ float d_feat[NA * 5];
__device__ float d_p[NA * HIDN], d_r[NA * HIDN];
__device__ float d_hpre[NA * HIDN];
__device__ float d_u[NA * HIDN], d_v[NA * HIDN];
__device__ float d_o2[NA * 2];
__device__ float d_gO[NA * 2];
__device__ float d_gts[NA * HIDN], d_gss[NA * HIDN];
__device__ float d_gh[NA * HIDN];
__device__ float d_wbuf[NA * HIDN];
__device__ float d_Bmod[NA], d_gBmod[NA], d_gBorn[NA], d_gS[NA];
__device__ float d_atomE[NA];
__device__ float d_gpos[NA * 3];
__device__ float d_energyM[NM];
__device__ float d_i1w2T[HIDN * HIDN];
__device__ float d_w1aT[HIDN * HIDN], d_w1bT[HIDN * HIDN];

__device__ __forceinline__ float sigm(float x) { return 1.0f / (1.0f + expf(-x)); }

__global__ void k_zero() {
    int i = blockIdx.x * blockDim.x + threadIdx.x;
    if (i < NA * HIDN) d_gss[i] = 0.0f;
    if (i < NA * 3)    d_gpos[i] = 0.0f;
    if (i < NM)        d_energyM[i] = 0.0f;
}

__global__ void k_scales(const float* ls, const float* le,
                         const float* stw1, const float* stb1, const float* stw2, const float* stb2,
                         const float* elw1, const float* elb1, const float* elw2, const float* elb2) {
    int m = threadIdx.x;
    if (m >= NM) return;
    float a = ls[m];
    float acc = stb2[0];
    for (int h = 0; h < 64; h++) {
        float z = a * stw1[h] + stb1[h];
        acc += (z * sigm(z)) * stw2[h];
    }
    d_scaleS[m] = sigm(acc) * a;
    float b = le[m];
    acc = elb2[0];
    for (int h = 0; h < 64; h++) {
        float z = b * elw1[h] + elb1[h];
        acc += (z * sigm(z)) * elw2[h];
    }
    d_scaleE[m] = sigm(acc) * b;
}

__global__ void k_transpose(const float* i1w2, const float* i2w1) {
    int idx = blockIdx.x * blockDim.x + threadIdx.x;
    const int n = HIDN * HIDN;
    if (idx < n) {
        int o = idx / HIDN, i = idx % HIDN;
        d_i1w2T[o * HIDN + i] = i1w2[i * HIDN + o];
    } else if (idx < 2 * n) {
        int r = idx - n;
        int j = r / HIDN, k = r % HIDN;
        d_w1aT[j * HIDN + k] = i2w1[k * HIDN + j];
    } else if (idx < 3 * n) {
        int r = idx - 2 * n;
        int j = r / HIDN, k = r % HIDN;
        d_w1bT[j * HIDN + k] = i2w1[(k + HIDN) * HIDN + j];
    }
}

__global__ void k_offsets(const int* gbdst, int Egb, const int* gdst, int Egnn) {
    int i = blockIdx.x * blockDim.x + threadIdx.x;
    if (i > NA) return;
    int lo = 0, hi = Egb;
    while (lo < hi) { int mid = (lo + hi) >> 1; if (gbdst[mid] < i) lo = mid + 1; else hi = mid; }
    d_gb_off[i] = lo;
    lo = 0; hi = Egnn;
    while (lo < hi) { int mid = (lo + hi) >> 1; if (gdst[mid] < i) lo = mid + 1; else hi = mid; }
    d_gnn_off[i] = lo;
}

// GB pass 1: distances + 0.5*I, psi partial sum (warp per target node)
__global__ void k_gb1(const float* pos, const float* gp, const int* src) {
    int w = (blockIdx.x * blockDim.x + threadIdx.x) >> 5;
    int lane = threadIdx.x & 31;
    if (w >= NA) return;
    int t = w;
    int beg = d_gb_off[t], end = d_gb_off[t + 1];
    float px = pos[3 * t], py = pos[3 * t + 1], pz = pos[3 * t + 2];
    float rho_t = gp[3 * t + 1];
    float S = 0.0f;
    for (int e = beg + lane; e < end; e += 32) {
        int s = src[e];
        float dx = pos[3 * s] - px, dy = pos[3 * s + 1] - py, dz = pos[3 * s + 2] - pz;
        float dd = sqrtf(dx * dx + dy * dy + dz * dz);
        d_edge_d[e] = dd;
        float sr = gp[3 * s + 2] * gp[3 * s + 1];
        float U = dd + sr;
        float t0 = dd - sr;
        float at = fabsf(t0);
        float L = fmaxf(at, rho_t);
        float invL = 1.0f / L, invU = 1.0f / U;
        float I = invL - invU
                + 0.25f * (dd - sr * sr / dd) * (invU * invU - invL * invL)
                + 0.5f * logf(L * invU) / dd;
        if (rho_t < sr - dd) I += 2.0f * (1.0f / rho_t - invL);
        S += 0.5f * I;
    }
    for (int o = 16; o; o >>= 1) S += __shfl_down_sync(0xffffffffu, S, o);
    if (lane == 0) d_psiS[t] = S;
}

__global__ void k_born(const float* gp) {
    int i = blockIdx.x * blockDim.x + threadIdx.x;
    if (i >= NA) return;
    float rho = gp[3 * i + 1], q = gp[3 * i];
    float psi = d_psiS[i] * rho;
    float u = psi - 0.8f * psi * psi + 4.85f * psi * psi * psi;
    float th = tanhf(u);
    float ro = rho + OFFS;
    float Dn = 1.0f / rho - th / ro;
    float B = 1.0f / Dn;
    float up = 1.0f - 1.6f * psi + 14.55f * psi * psi;
    d_Born[i] = B;
    d_dBdS[i] = B * B * (1.0f - th * th) * up / ro * rho;
    int m = i >> 8;
    d_feat[5 * i + 0] = B;
    d_feat[5 * i + 1] = q;
    d_feat[5 * i + 2] = rho;
    d_feat[5 * i + 3] = d_scaleS[m];
    d_feat[5 * i + 4] = d_scaleE[m];
}

// p = f@W1[0:5,:], r = f@W1[5:10,:]
__global__ void k_pr(const float* w1) {
    int idx = blockIdx.x * blockDim.x + threadIdx.x;
    if (idx >= NA * HIDN) return;
    int i = idx / HIDN, j = idx % HIDN;
    const float* f = &d_feat[5 * i];
    float p = 0.0f, rv = 0.0f;
#pragma unroll
    for (int k = 0; k < 5; k++) {
        p  += f[k] * w1[k * HIDN + j];
        rv += f[k] * w1[(5 + k) * HIDN + j];
    }
    d_p[idx] = p;
    d_r[idx] = rv;
}

// layer1 fwd fused: z = sum silu(p[s]+r[t]+b1); hpre = z@W2 + deg*b2; h=silu; u=h@W1a, v=h@W1b
__global__ void k_l1fwd(const int* gsrc, const float* b1, const float* w2, const float* b2,
                        const float* i2w1) {
    int t = blockIdx.x, j = threadIdx.x;
    __shared__ float sh[HIDN];
    int beg = d_gnn_off[t], end = d_gnn_off[t + 1];
    float rj = d_r[t * HIDN + j] + b1[j];
    float z = 0.0f;
    for (int e = beg; e < end; e++) {
        int s = gsrc[e];
        float a = d_p[s * HIDN + j] + rj;
        z += a * sigm(a);
    }
    sh[j] = z;
    __syncthreads();
    float deg = (float)(end - beg);
    float acc = deg * b2[j];
    for (int k = 0; k < HIDN; k++) acc += sh[k] * w2[k * HIDN + j];
    d_hpre[t * HIDN + j] = acc;
    float h = acc * sigm(acc);
    __syncthreads();
    sh[j] = h;
    __syncthreads();
    float uu = 0.0f, vv = 0.0f;
    for (int k = 0; k < HIDN; k++) {
        float hk = sh[k];
        uu += hk * i2w1[k * HIDN + j];
        vv += hk * i2w1[(k + HIDN) * HIDN + j];
    }
    d_u[t * HIDN + j] = uu;
    d_v[t * HIDN + j] = vv;
}

__global__ void k_l2fwd(const int* gsrc, const float* b1, const float* w2, const float* b2) {
    int t = blockIdx.x, j = threadIdx.x;
    __shared__ float red0[256], red1[256];
    int beg = d_gnn_off[t], end = d_gnn_off[t + 1];
    float vj = d_v[t * HIDN + j] + b1[j];
    float s2 = 0.0f;
    for (int e = beg; e < end; e++) {
        int s = gsrc[e];
        float a = d_u[s * HIDN + j] + vj;
        s2 += a * sigm(a);
    }
    red0[j] = s2 * w2[2 * j];
    red1[j] = s2 * w2[2 * j + 1];
    if (j < 64) { red0[HIDN + j] = 0.0f; red1[HIDN + j] = 0.0f; }
    __syncthreads();
    for (int st = 128; st > 0; st >>= 1) {
        if (j < st) { red0[j] += red0[j + st]; red1[j] += red1[j + st]; }
        __syncthreads();
    }
    if (j == 0) {
        float deg = (float)(end - beg);
        d_o2[2 * t]     = red0[0] + deg * b2[0];
        d_o2[2 * t + 1] = red1[0] + deg * b2[1];
    }
}

__global__ void k_post(const float* gp) {
    int i = blockIdx.x * blockDim.x + threadIdx.x;
    if (i >= NA) return;
    float c = d_o2[2 * i];
    float sg = sigm(c);
    float sc = 0.5f + sg;
    float B = d_Born[i];
    float Bm = B * sc;
    d_Bmod[i] = Bm;
    float rho = gp[3 * i + 1], q = gp[3 * i];
    float rr = rho + OFFS + 0.14f;
    float sa = d_o2[2 * i + 1];
    float sa_e = SACONST * sa * rr * rr;
    float self_e = 0.5f * PREF * q * q / Bm;
    int m = i >> 8;
    float lee = d_scaleE[m], lss = d_scaleS[m];
    d_atomE[i] = lee * self_e + lss * sa_e;
    d_gBmod[i] = -lee * 0.5f * PREF * q * q / (Bm * Bm);
}

// pair energy fwd + adjoints wrt Bmod and d (warp per target node)
__global__ void k_pair(const float* gp, const int* src) {
    int w = (blockIdx.x * blockDim.x + threadIdx.x) >> 5;
    int lane = threadIdx.x & 31;
    if (w >= NA) return;
    int t = w;
    int beg = d_gb_off[t], end = d_gb_off[t + 1];
    float Bt = d_Bmod[t];
    float qt = gp[3 * t];
    float let_ = d_scaleE[t >> 8];
    float C0 = 0.5f * PREF * let_ * qt;
    float epair = 0.0f, gBt = 0.0f;
    for (int e = beg + lane; e < end; e += 32) {
        int s = src[e];
        float dd = d_edge_d[e];
        float Bs = d_Bmod[s];
        float B = Bs * Bt;
        float d2 = dd * dd;
        float x = d2 / (4.0f * B);
        float ex = expf(-x);
        float f2 = d2 + B * ex;
        float fgb = sqrtf(f2);
        float C = C0 * gp[3 * s];
        epair += C / fgb;
        float gf = -C / f2 / fgb * fgb;   // = -C/f2 (dE/dfgb * fgb/fgb kept simple)
        gf = -C / f2;
        float dfdB = ex * (1.0f + x) / (2.0f * fgb);
        float dfdd = dd * (1.0f - 0.25f * ex) / fgb;
        d_gd[e] = gf * dfdd;
        float gB = gf * dfdB;
        atomicAdd(&d_gBmod[s], gB * Bt);
        gBt += gB * Bs;
    }
    for (int o = 16; o; o >>= 1) {
        epair += __shfl_down_sync(0xffffffffu, epair, o);
        gBt   += __shfl_down_sync(0xffffffffu, gBt, o);
    }
    if (lane == 0) {
        atomicAdd(&d_atomE[t], epair);
        atomicAdd(&d_gBmod[t], gBt);
    }
}

__global__ void k_gO(const float* gp) {
    int i = blockIdx.x * blockDim.x + threadIdx.x;
    if (i >= NA) return;
    float c = d_o2[2 * i];
    float sg = sigm(c);
    float gB = d_gBmod[i];
    float B = d_Born[i];
    d_gO[2 * i] = gB * B * sg * (1.0f - sg);
    float rho = gp[3 * i + 1];
    float rr = rho + OFFS + 0.14f;
    int m = i >> 8;
    d_gO[2 * i + 1] = d_scaleS[m] * SACONST * rr * rr;
    d_gBorn[i] = gB * (0.5f + sg);
}

// layer2 bwd: per target t, g_a2 per edge; accumulate gts locally, gss[s] via atomics
__global__ void k_l2bwd(const int* gsrc, const float* b1, const float* w2) {
    int t = blockIdx.x, j = threadIdx.x;
    int beg = d_gnn_off[t], end = d_gnn_off[t + 1];
    float g0 = d_gO[2 * t], g1 = d_gO[2 * t + 1];
    float gs2 = g0 * w2[2 * j] + g1 * w2[2 * j + 1];
    float vj = d_v[t * HIDN + j] + b1[j];
    float gts = 0.0f;
    for (int e = beg; e < end; e++) {
        int s = gsrc[e];
        float a = d_u[s * HIDN + j] + vj;
        float sg = sigm(a);
        float sp = sg * (1.0f + a * (1.0f - sg));
        float ga = gs2 * sp;
        gts += ga;
        atomicAdd(&d_gss[s * HIDN + j], ga);
    }
    d_gts[t * HIDN + j] = gts;
}

// g_h = g_u@W1a^T + g_v@W1b^T
__global__ void k_ghgemm() {
    int i = blockIdx.x, k = threadIdx.x;
    __shared__ float ss[HIDN], stt[HIDN];
    ss[k]  = d_gss[i * HIDN + k];
    stt[k] = d_gts[i * HIDN + k];
    __syncthreads();
    float acc = 0.0f;
    for (int j = 0; j < HIDN; j++)
        acc += ss[j] * d_w1aT[j * HIDN + k] + stt[j] * d_w1bT[j * HIDN + k];
    d_gh[i * HIDN + k] = acc;
}

// g_hpre = g_h * silu'(hpre); wbuf = g_hpre @ i1w2^T
__global__ void k_wbuf() {
    int t = blockIdx.x, j = threadIdx.x;
    __shared__ float sh[HIDN];
    float hp = d_hpre[t * HIDN + j];
    float sg = sigm(hp);
    float sp = sg * (1.0f + hp * (1.0f - sg));
    sh[j] = d_gh[t * HIDN + j] * sp;
    __syncthreads();
    float acc = 0.0f;
    for (int o = 0; o < HIDN; o++) acc += sh[o] * d_i1w2T[o * HIDN + j];
    d_wbuf[t * HIDN + j] = acc;
}

// layer1 bwd: only Born (feat dim 0) matters -> W1 rows 0 and 5 (warp per gnn edge)
__global__ void k_l1bwd(const int* gsrc, const int* gdst, const float* b1, const float* w1, int E) {
    int e = (blockIdx.x * blockDim.x + threadIdx.x) >> 5;
    int lane = threadIdx.x & 31;
    if (e >= E) return;
    int s = gsrc[e], t = gdst[e];
    float s0 = 0.0f, s5 = 0.0f;
#pragma unroll
    for (int c = 0; c < 6; c++) {
        int j = lane + 32 * c;
        float a = d_p[s * HIDN + j] + d_r[t * HIDN + j] + b1[j];
        float sg = sigm(a);
        float sp = sg * (1.0f + a * (1.0f - sg));
        float ga = d_wbuf[t * HIDN + j] * sp;
        s0 += ga * w1[j];
        s5 += ga * w1[5 * HIDN + j];
    }
    for (int o = 16; o; o >>= 1) {
        s0 += __shfl_down_sync(0xffffffffu, s0, o);
        s5 += __shfl_down_sync(0xffffffffu, s5, o);
    }
    if (lane == 0) {
        atomicAdd(&d_gBorn[s], s0);
        atomicAdd(&d_gBorn[t], s5);
    }
}

__global__ void k_gS() {
    int i = blockIdx.x * blockDim.x + threadIdx.x;
    if (i >= NA) return;
    d_gS[i] = d_gBorn[i] * d_dBdS[i];
}

// GB bwd: dI/dd + fgb d-adjoint -> position gradients (warp per target node)
__global__ void k_gbbwd(const float* pos, const float* gp, const int* src) {
    int w = (blockIdx.x * blockDim.x + threadIdx.x) >> 5;
    int lane = threadIdx.x & 31;
    if (w >= NA) return;
    int t = w;
    int beg = d_gb_off[t], end = d_gb_off[t + 1];
    float px = pos[3 * t], py = pos[3 * t + 1], pz = pos[3 * t + 2];
    float rho_t = gp[3 * t + 1];
    float gst = d_gS[t];
    float fx = 0.0f, fy = 0.0f, fz = 0.0f;
    for (int e = beg + lane; e < end; e += 32) {
        int s = src[e];
        float dd = d_edge_d[e];
        float sr = gp[3 * s + 2] * gp[3 * s + 1];
        float t0 = dd - sr;
        float at = fabsf(t0);
        float L = fmaxf(at, rho_t);
        float Lp = (at > rho_t) ? (t0 > 0.0f ? 1.0f : -1.0f) : 0.0f;
        float invL = 1.0f / L, invU = 1.0f / (dd + sr);
        float dA = -Lp * invL * invL + invU * invU;
        float P  = 0.25f * (dd - sr * sr / dd);
        float Pp = 0.25f * (1.0f + sr * sr / (dd * dd));
        float Q  = invU * invU - invL * invL;
        float Qp = -2.0f * invU * invU * invU + 2.0f * Lp * invL * invL * invL;
        float dC = 0.5f * ((Lp * invL - invU) / dd - logf(L * invU) / (dd * dd));
        float extra = (rho_t < sr - dd) ? 2.0f * Lp * invL * invL : 0.0f;
        float Ip = 0.5f * (dA + Pp * Q + P * Qp + dC + extra);
        float g = d_gd[e] + gst * Ip;
        float c = g / dd;
        float dx = pos[3 * s] - px, dy = pos[3 * s + 1] - py, dz = pos[3 * s + 2] - pz;
        atomicAdd(&d_gpos[3 * s],     c * dx);
        atomicAdd(&d_gpos[3 * s + 1], c * dy);
        atomicAdd(&d_gpos[3 * s + 2], c * dz);
        fx -= c * dx; fy -= c * dy; fz -= c * dz;
    }
    for (int o = 16; o; o >>= 1) {
        fx += __shfl_down_sync(0xffffffffu, fx, o);
        fy += __shfl_down_sync(0xffffffffu, fy, o);
        fz += __shfl_down_sync(0xffffffffu, fz, o);
    }
    if (lane == 0) {
        atomicAdd(&d_gpos[3 * t],     fx);
        atomicAdd(&d_gpos[3 * t + 1], fy);
        atomicAdd(&d_gpos[3 * t + 2], fz);
    }
}

__global__ void k_out(float* out) {
    int i = blockIdx.x * blockDim.x + threadIdx.x;
    if (i >= NA) return;
    out[NM + 3 * i]     = -d_gpos[3 * i];
    out[NM + 3 * i + 1] = -d_gpos[3 * i + 1];
    out[NM + 3 * i + 2] = -d_gpos[3 * i + 2];
    atomicAdd(&d_energyM[i >> 8], d_atomE[i]);
}

__global__ void k_eout(float* out) {
    int m = threadIdx.x;
    if (m < NM) out[m] = d_energyM[m];
}

extern "C" void kernel_launch(void* const* d_in, const int* in_sizes, int n_in,
                              void* d_out, int out_size) {
    const float* pos  = (const float*)d_in[0];
    const float* ls   = (const float*)d_in[1];
    const float* le   = (const float*)d_in[2];
    const float* gp   = (const float*)d_in[3];
    const float* stw1 = (const float*)d_in[4];
    const float* stb1 = (const float*)d_in[5];
    const float* stw2 = (const float*)d_in[6];
    const float* stb2 = (const float*)d_in[7];
    const float* elw1 = (const float*)d_in[8];
    const float* elb1 = (const float*)d_in[9];
    const float* elw2 = (const float*)d_in[10];
    const float* elb2 = (const float*)d_in[11];
    const float* i1w1 = (const float*)d_in[12];
    const float* i1b1 = (const float*)d_in[13];
    const float* i1w2 = (const float*)d_in[14];
    const float* i1b2 = (const float*)d_in[15];
    const float* i2w1 = (const float*)d_in[16];
    const float* i2b1 = (const float*)d_in[17];
    const float* i2w2 = (const float*)d_in[18];
    const float* i2b2 = (const float*)d_in[19];
    const int*   ei   = (const int*)d_in[21];
    const int*   gei  = (const int*)d_in[22];
    float* out = (float*)d_out;

    int Egb  = in_sizes[21] / 2;
    int Egnn = in_sizes[22] / 2;
    const int* gbsrc = ei;
    const int* gbdst = ei + Egb;
    const int* gsrc  = gei;
    const int* gdst  = gei + Egnn;

    k_zero<<<(NA * HIDN + 255) / 256, 256>>>();
    k_scales<<<1, 64>>>(ls, le, stw1, stb1, stw2, stb2, elw1, elb1, elw2, elb2);
    k_transpose<<<(3 * HIDN * HIDN + 255) / 256, 256>>>(i1w2, i2w1);
    k_offsets<<<(NA + 256) / 256, 256>>>(gbdst, Egb, gdst, Egnn);
    k_gb1<<<(NA * 32 + 255) / 256, 256>>>(pos, gp, gbsrc);
    k_born<<<(NA + 255) / 256, 256>>>(gp);
    k_pr<<<(NA * HIDN + 255) / 256, 256>>>(i1w1);
    k_l1fwd<<<NA, HIDN>>>(gsrc, i1b1, i1w2, i1b2, i2w1);
    k_l2fwd<<<NA, HIDN>>>(gsrc, i2b1, i2w2, i2b2);
    k_post<<<(NA + 255) / 256, 256>>>(gp);
    k_pair<<<(NA * 32 + 255) / 256, 256>>>(gp, gbsrc);
    k_gO<<<(NA + 255) / 256, 256>>>(gp);
    k_l2bwd<<<NA, HIDN>>>(gsrc, i2b1, i2w2);
    k_ghgemm<<<NA, HIDN>>>();
    k_wbuf<<<NA, HIDN>>>();
    k_l1bwd<<<(Egnn * 32 + 255) / 256, 256>>>(gsrc, gdst, i1b1, i1w1, Egnn);
    k_gS<<<(NA + 255) / 256, 256>>>();
    k_gbbwd<<<(NA * 32 + 255) / 256, 256>>>(pos, gp, gbsrc);
    k_out<<<(NA + 255) / 256, 256>>>(out);
    k_eout<<<1, 64>>>(out);
}

// round 3
// speedup vs baseline: 1.4217x; 1.4217x over previous
#include <cuda_runtime.h>
#include <math.h>

#define NM 64
#define NA 16384
#define HIDN 192
#define EMAX 524288
#define OFFS 0.0195141f
#define PREF (-138.935485f * (1.0f - 1.0f/78.5f))
#define SACONST (4.184f * 0.00542f * 100.0f)

__device__ float d_scaleS[NM], d_scaleE[NM];
__device__ int   d_gb_off[NA + 1], d_gnn_off[NA + 1];
__device__ float d_edge_d[EMAX];
__device__ float d_gd[EMAX];
__device__ float d_psiS[NA];
__device__ float d_Born[NA], d_dBdS[NA];
__device__ float d_feat[NA * 5];
__device__ float d_p[NA * HIDN], d_r[NA * HIDN];
__device__ float d_hpre[NA * HIDN];
__device__ float d_u[NA * HIDN], d_v[NA * HIDN];
__device__ float d_o2[NA * 2];
__device__ float d_gO[NA * 2];
__device__ float d_wbuf[NA * HIDN];
__device__ float d_Bmod[NA], d_gBmod[NA], d_gBorn[NA], d_gS[NA];
__device__ float d_atomE[NA];
__device__ float d_gpos[NA * 3];
__device__ float d_i1w2T[HIDN * HIDN];
__device__ float d_w1aT[HIDN * HIDN], d_w1bT[HIDN * HIDN];

__device__ __forceinline__ float sigm(float x) { return 1.0f / (1.0f + expf(-x)); }

// ---------------- fused setup: scales | zero gpos | transposes | CSR offsets (O(E) scatter) ----
__global__ void k_setup(const float* ls, const float* le,
                        const float* stw1, const float* stb1, const float* stw2, const float* stb2,
                        const float* elw1, const float* elb1, const float* elw2, const float* elb2,
                        const float* i1w2, const float* i2w1,
                        const int* gbdst, int Egb, const int* gdst, int Egnn) {
    int idx = blockIdx.x * blockDim.x + threadIdx.x;
    const int n = HIDN * HIDN;
    if (idx < NM) {
        int m = idx;
        float a = ls[m];
        float acc = stb2[0];
        for (int h = 0; h < 64; h++) {
            float z = a * stw1[h] + stb1[h];
            acc += (z * sigm(z)) * stw2[h];
        }
        d_scaleS[m] = sigm(acc) * a;
        float b = le[m];
        acc = elb2[0];
        for (int h = 0; h < 64; h++) {
            float z = b * elw1[h] + elb1[h];
            acc += (z * sigm(z)) * elw2[h];
        }
        d_scaleE[m] = sigm(acc) * b;
        return;
    }
    idx -= NM;
    if (idx < NA * 3) { d_gpos[idx] = 0.0f; return; }
    idx -= NA * 3;
    if (idx < n) { int o = idx / HIDN, i = idx % HIDN; d_i1w2T[o * HIDN + i] = i1w2[i * HIDN + o]; return; }
    idx -= n;
    if (idx < n) { int j = idx / HIDN, k = idx % HIDN; d_w1aT[j * HIDN + k] = i2w1[k * HIDN + j]; return; }
    idx -= n;
    if (idx < n) { int j = idx / HIDN, k = idx % HIDN; d_w1bT[j * HIDN + k] = i2w1[(k + HIDN) * HIDN + j]; return; }
    idx -= n;
    if (idx < Egb) {
        int e = idx;
        int dc = gbdst[e];
        if (e == 0) { for (int i = 0; i <= dc; i++) d_gb_off[i] = 0; }
        else { int dp = gbdst[e - 1]; for (int i = dp + 1; i <= dc; i++) d_gb_off[i] = e; }
        if (e == Egb - 1) { for (int i = dc + 1; i <= NA; i++) d_gb_off[i] = Egb; }
        return;
    }
    idx -= Egb;
    if (idx < Egnn) {
        int e = idx;
        int dc = gdst[e];
        if (e == 0) { for (int i = 0; i <= dc; i++) d_gnn_off[i] = 0; }
        else { int dp = gdst[e - 1]; for (int i = dp + 1; i <= dc; i++) d_gnn_off[i] = e; }
        if (e == Egnn - 1) { for (int i = dc + 1; i <= NA; i++) d_gnn_off[i] = Egnn; }
        return;
    }
}

// ---------------- GB pass 1: distances + 0.5*I, psi sum (warp per target node) ----------------
__global__ void k_gb1(const float* pos, const float* gp, const int* src) {
    int w = (blockIdx.x * blockDim.x + threadIdx.x) >> 5;
    int lane = threadIdx.x & 31;
    if (w >= NA) return;
    int t = w;
    int beg = d_gb_off[t], end = d_gb_off[t + 1];
    float px = pos[3 * t], py = pos[3 * t + 1], pz = pos[3 * t + 2];
    float rho_t = gp[3 * t + 1];
    float S = 0.0f;
    for (int e = beg + lane; e < end; e += 32) {
        int s = src[e];
        float dx = pos[3 * s] - px, dy = pos[3 * s + 1] - py, dz = pos[3 * s + 2] - pz;
        float dd = sqrtf(dx * dx + dy * dy + dz * dz);
        d_edge_d[e] = dd;
        float sr = gp[3 * s + 2] * gp[3 * s + 1];
        float U = dd + sr;
        float t0 = dd - sr;
        float at = fabsf(t0);
        float L = fmaxf(at, rho_t);
        float invL = 1.0f / L, invU = 1.0f / U;
        float I = invL - invU
                + 0.25f * (dd - sr * sr / dd) * (invU * invU - invL * invL)
                + 0.5f * logf(L * invU) / dd;
        if (rho_t < sr - dd) I += 2.0f * (1.0f / rho_t - invL);
        S += 0.5f * I;
    }
    for (int o = 16; o; o >>= 1) S += __shfl_down_sync(0xffffffffu, S, o);
    if (lane == 0) d_psiS[t] = S;
}

__global__ void k_born(const float* gp) {
    int i = blockIdx.x * blockDim.x + threadIdx.x;
    if (i >= NA) return;
    float rho = gp[3 * i + 1], q = gp[3 * i];
    float psi = d_psiS[i] * rho;
    float u = psi - 0.8f * psi * psi + 4.85f * psi * psi * psi;
    float th = tanhf(u);
    float ro = rho + OFFS;
    float Dn = 1.0f / rho - th / ro;
    float B = 1.0f / Dn;
    float up = 1.0f - 1.6f * psi + 14.55f * psi * psi;
    d_Born[i] = B;
    d_dBdS[i] = B * B * (1.0f - th * th) * up / ro * rho;
    int m = i >> 8;
    d_feat[5 * i + 0] = B;
    d_feat[5 * i + 1] = q;
    d_feat[5 * i + 2] = rho;
    d_feat[5 * i + 3] = d_scaleS[m];
    d_feat[5 * i + 4] = d_scaleE[m];
}

// p = f@W1[0:5,:], r = f@W1[5:10,:]
__global__ void k_pr(const float* w1) {
    int idx = blockIdx.x * blockDim.x + threadIdx.x;
    if (idx >= NA * HIDN) return;
    int i = idx / HIDN, j = idx % HIDN;
    const float* f = &d_feat[5 * i];
    float p = 0.0f, rv = 0.0f;
#pragma unroll
    for (int k = 0; k < 5; k++) {
        p  += f[k] * w1[k * HIDN + j];
        rv += f[k] * w1[(5 + k) * HIDN + j];
    }
    d_p[idx] = p;
    d_r[idx] = rv;
}

// ---------------- layer1 fwd, 4 nodes per block (weight-load amortization) ----------------
__global__ void k_l1fwd(const int* gsrc, const float* b1, const float* w2, const float* b2,
                        const float* i2w1) {
    int j = threadIdx.x;
    int base = blockIdx.x * 4;
    __shared__ float sh[HIDN * 4];
    float b1j = b1[j];
    float z[4], deg[4];
#pragma unroll
    for (int nn = 0; nn < 4; nn++) {
        int t = base + nn;
        int beg = d_gnn_off[t], end = d_gnn_off[t + 1];
        deg[nn] = (float)(end - beg);
        float rj = d_r[t * HIDN + j] + b1j;
        float zz = 0.0f;
        for (int e = beg; e < end; e++) {
            int s = gsrc[e];
            float a = d_p[s * HIDN + j] + rj;
            zz += a * sigm(a);
        }
        z[nn] = zz;
    }
    *(float4*)&sh[j * 4] = make_float4(z[0], z[1], z[2], z[3]);
    __syncthreads();
    float b2j = b2[j];
    float a0 = deg[0] * b2j, a1 = deg[1] * b2j, a2 = deg[2] * b2j, a3 = deg[3] * b2j;
    for (int k = 0; k < HIDN; k++) {
        float4 zv = *(const float4*)&sh[k * 4];
        float w = w2[k * HIDN + j];
        a0 += zv.x * w; a1 += zv.y * w; a2 += zv.z * w; a3 += zv.w * w;
    }
    d_hpre[(base + 0) * HIDN + j] = a0;
    d_hpre[(base + 1) * HIDN + j] = a1;
    d_hpre[(base + 2) * HIDN + j] = a2;
    d_hpre[(base + 3) * HIDN + j] = a3;
    float h0 = a0 * sigm(a0), h1 = a1 * sigm(a1), h2 = a2 * sigm(a2), h3 = a3 * sigm(a3);
    __syncthreads();
    *(float4*)&sh[j * 4] = make_float4(h0, h1, h2, h3);
    __syncthreads();
    float u0 = 0, u1 = 0, u2 = 0, u3 = 0, v0 = 0, v1 = 0, v2 = 0, v3 = 0;
    for (int k = 0; k < HIDN; k++) {
        float4 hv = *(const float4*)&sh[k * 4];
        float wa = i2w1[k * HIDN + j];
        float wb = i2w1[(k + HIDN) * HIDN + j];
        u0 += hv.x * wa; u1 += hv.y * wa; u2 += hv.z * wa; u3 += hv.w * wa;
        v0 += hv.x * wb; v1 += hv.y * wb; v2 += hv.z * wb; v3 += hv.w * wb;
    }
    d_u[(base + 0) * HIDN + j] = u0; d_v[(base + 0) * HIDN + j] = v0;
    d_u[(base + 1) * HIDN + j] = u1; d_v[(base + 1) * HIDN + j] = v1;
    d_u[(base + 2) * HIDN + j] = u2; d_v[(base + 2) * HIDN + j] = v2;
    d_u[(base + 3) * HIDN + j] = u3; d_v[(base + 3) * HIDN + j] = v3;
}

__global__ void k_l2fwd(const int* gsrc, const float* b1, const float* w2, const float* b2) {
    int t = blockIdx.x, j = threadIdx.x;
    __shared__ float red0[256], red1[256];
    int beg = d_gnn_off[t], end = d_gnn_off[t + 1];
    float vj = d_v[t * HIDN + j] + b1[j];
    float s2 = 0.0f;
    for (int e = beg; e < end; e++) {
        int s = gsrc[e];
        float a = d_u[s * HIDN + j] + vj;
        s2 += a * sigm(a);
    }
    red0[j] = s2 * w2[2 * j];
    red1[j] = s2 * w2[2 * j + 1];
    if (j < 64) { red0[HIDN + j] = 0.0f; red1[HIDN + j] = 0.0f; }
    __syncthreads();
    for (int st = 128; st > 0; st >>= 1) {
        if (j < st) { red0[j] += red0[j + st]; red1[j] += red1[j + st]; }
        __syncthreads();
    }
    if (j == 0) {
        float deg = (float)(end - beg);
        d_o2[2 * t]     = red0[0] + deg * b2[0];
        d_o2[2 * t + 1] = red1[0] + deg * b2[1];
    }
}

__global__ void k_post(const float* gp) {
    int i = blockIdx.x * blockDim.x + threadIdx.x;
    if (i >= NA) return;
    float c = d_o2[2 * i];
    float sg = sigm(c);
    float sc = 0.5f + sg;
    float B = d_Born[i];
    float Bm = B * sc;
    d_Bmod[i] = Bm;
    float rho = gp[3 * i + 1], q = gp[3 * i];
    float rr = rho + OFFS + 0.14f;
    float sa = d_o2[2 * i + 1];
    float sa_e = SACONST * sa * rr * rr;
    float self_e = 0.5f * PREF * q * q / Bm;
    int m = i >> 8;
    float lee = d_scaleE[m], lss = d_scaleS[m];
    d_atomE[i] = lee * self_e + lss * sa_e;
    d_gBmod[i] = -lee * 0.5f * PREF * q * q / (Bm * Bm);
}

// pair energy fwd + adjoints wrt Bmod and d (warp per target node)
__global__ void k_pair(const float* gp, const int* src) {
    int w = (blockIdx.x * blockDim.x + threadIdx.x) >> 5;
    int lane = threadIdx.x & 31;
    if (w >= NA) return;
    int t = w;
    int beg = d_gb_off[t], end = d_gb_off[t + 1];
    float Bt = d_Bmod[t];
    float qt = gp[3 * t];
    float let_ = d_scaleE[t >> 8];
    float C0 = 0.5f * PREF * let_ * qt;
    float epair = 0.0f, gBt = 0.0f;
    for (int e = beg + lane; e < end; e += 32) {
        int s = src[e];
        float dd = d_edge_d[e];
        float Bs = d_Bmod[s];
        float B = Bs * Bt;
        float d2 = dd * dd;
        float x = d2 / (4.0f * B);
        float ex = expf(-x);
        float f2 = d2 + B * ex;
        float fgb = sqrtf(f2);
        float C = C0 * gp[3 * s];
        epair += C / fgb;
        float gf = -C / f2;
        float dfdB = ex * (1.0f + x) / (2.0f * fgb);
        float dfdd = dd * (1.0f - 0.25f * ex) / fgb;
        d_gd[e] = gf * dfdd;
        float gB = gf * dfdB;
        atomicAdd(&d_gBmod[s], gB * Bt);
        gBt += gB * Bs;
    }
    for (int o = 16; o; o >>= 1) {
        epair += __shfl_down_sync(0xffffffffu, epair, o);
        gBt   += __shfl_down_sync(0xffffffffu, gBt, o);
    }
    if (lane == 0) {
        atomicAdd(&d_atomE[t], epair);
        atomicAdd(&d_gBmod[t], gBt);
    }
}

__global__ void k_gO(const float* gp) {
    int i = blockIdx.x * blockDim.x + threadIdx.x;
    if (i >= NA) return;
    float c = d_o2[2 * i];
    float sg = sigm(c);
    float gB = d_gBmod[i];
    float B = d_Born[i];
    d_gO[2 * i] = gB * B * sg * (1.0f - sg);
    float rho = gp[3 * i + 1];
    float rr = rho + OFFS + 0.14f;
    int m = i >> 8;
    d_gO[2 * i + 1] = d_scaleS[m] * SACONST * rr * rr;
    d_gBorn[i] = gB * (0.5f + sg);
}

// ---------------- fused GNN backward: gss/gts gather (symmetric graph, no atomics),
// gh = gss@W1aT + gts@W1bT, g_hpre, wbuf = g_hpre@i1w2T.  2 nodes per block. ----------------
__global__ void k_bwd(const int* gsrc, const float* b1, const float* w2) {
    int j = threadIdx.x;
    int i0 = blockIdx.x * 2;
    __shared__ float sh[HIDN * 4];
    float b1j = b1[j];
    float w20 = w2[2 * j], w21 = w2[2 * j + 1];
    float gssv[2], gtsv[2];
#pragma unroll
    for (int n2 = 0; n2 < 2; n2++) {
        int i = i0 + n2;
        int beg = d_gnn_off[i], end = d_gnn_off[i + 1];
        float vi = d_v[i * HIDN + j] + b1j;
        float ui = d_u[i * HIDN + j];
        float g0 = d_gO[2 * i], g1 = d_gO[2 * i + 1];
        float gs2i = g0 * w20 + g1 * w21;
        float sT = 0.0f, sS = 0.0f;
        for (int e = beg; e < end; e++) {
            int s = gsrc[e];
            float un = d_u[s * HIDN + j];
            float vn = d_v[s * HIDN + j];
            float a = un + vi;                       // tgt-side: u[n]+v[i]+b1
            float sg = sigm(a);
            sT += sg * (1.0f + a * (1.0f - sg));
            float a2 = ui + vn + b1j;                // src-side: u[i]+v[n]+b1
            float sg2 = sigm(a2);
            float sp2 = sg2 * (1.0f + a2 * (1.0f - sg2));
            float gn0 = d_gO[2 * s], gn1 = d_gO[2 * s + 1];
            sS += (gn0 * w20 + gn1 * w21) * sp2;
        }
        gtsv[n2] = gs2i * sT;
        gssv[n2] = sS;
    }
    *(float4*)&sh[j * 4] = make_float4(gssv[0], gtsv[0], gssv[1], gtsv[1]);
    __syncthreads();
    float gh0 = 0.0f, gh1 = 0.0f;
    for (int k = 0; k < HIDN; k++) {
        float4 q = *(const float4*)&sh[k * 4];
        float wa = d_w1aT[k * HIDN + j];
        float wb = d_w1bT[k * HIDN + j];
        gh0 += q.x * wa + q.y * wb;
        gh1 += q.z * wa + q.w * wb;
    }
    float hp0 = d_hpre[i0 * HIDN + j];
    float sg = sigm(hp0);
    gh0 *= sg * (1.0f + hp0 * (1.0f - sg));
    float hp1 = d_hpre[(i0 + 1) * HIDN + j];
    sg = sigm(hp1);
    gh1 *= sg * (1.0f + hp1 * (1.0f - sg));
    __syncthreads();
    *(float2*)&sh[j * 2] = make_float2(gh0, gh1);
    __syncthreads();
    float wb0 = 0.0f, wb1 = 0.0f;
    for (int k = 0; k < HIDN; k++) {
        float2 g = *(const float2*)&sh[k * 2];
        float ww = d_i1w2T[k * HIDN + j];
        wb0 += g.x * ww; wb1 += g.y * ww;
    }
    d_wbuf[i0 * HIDN + j]       = wb0;
    d_wbuf[(i0 + 1) * HIDN + j] = wb1;
}

// ---------------- layer1 bwd via symmetry (block per node, no atomics) + fold gS ----------------
__global__ void k_l1bwd(const int* gsrc, const float* b1, const float* w1) {
    int i = blockIdx.x, j = threadIdx.x;
    __shared__ float red[HIDN];
    int beg = d_gnn_off[i], end = d_gnn_off[i + 1];
    float b1j = b1[j];
    float pi = d_p[i * HIDN + j];
    float ri = d_r[i * HIDN + j] + b1j;
    float wbi = d_wbuf[i * HIDN + j];
    float accA = 0.0f, accB = 0.0f;
    for (int e = beg; e < end; e++) {
        int s = gsrc[e];
        float rn = d_r[s * HIDN + j];
        float pn = d_p[s * HIDN + j];
        float wbn = d_wbuf[s * HIDN + j];
        float aO = pi + rn + b1j;                    // i as src, n as tgt
        float sg = sigm(aO);
        accA += wbn * (sg * (1.0f + aO * (1.0f - sg)));
        float aI = pn + ri;                          // n as src, i as tgt
        float sg2 = sigm(aI);
        accB += sg2 * (1.0f + aI * (1.0f - sg2));
    }
    red[j] = accA * w1[j] + wbi * accB * w1[5 * HIDN + j];
    __syncthreads();
    if (j < 96) red[j] += red[j + 96];
    __syncthreads();
    if (j < 32) {
        float v = red[j] + red[j + 32] + red[j + 64];
        for (int o = 16; o; o >>= 1) v += __shfl_down_sync(0xffffffffu, v, o);
        if (j == 0) d_gS[i] = (d_gBorn[i] + v) * d_dBdS[i];
    }
}

// GB bwd: dI/dd + fgb d-adjoint -> position gradients (warp per target node)
__global__ void k_gbbwd(const float* pos, const float* gp, const int* src) {
    int w = (blockIdx.x * blockDim.x + threadIdx.x) >> 5;
    int lane = threadIdx.x & 31;
    if (w >= NA) return;
    int t = w;
    int beg = d_gb_off[t], end = d_gb_off[t + 1];
    float px = pos[3 * t], py = pos[3 * t + 1], pz = pos[3 * t + 2];
    float rho_t = gp[3 * t + 1];
    float gst = d_gS[t];
    float fx = 0.0f, fy = 0.0f, fz = 0.0f;
    for (int e = beg + lane; e < end; e += 32) {
        int s = src[e];
        float dd = d_edge_d[e];
        float sr = gp[3 * s + 2] * gp[3 * s + 1];
        float t0 = dd - sr;
        float at = fabsf(t0);
        float L = fmaxf(at, rho_t);
        float Lp = (at > rho_t) ? (t0 > 0.0f ? 1.0f : -1.0f) : 0.0f;
        float invL = 1.0f / L, invU = 1.0f / (dd + sr);
        float dA = -Lp * invL * invL + invU * invU;
        float P  = 0.25f * (dd - sr * sr / dd);
        float Pp = 0.25f * (1.0f + sr * sr / (dd * dd));
        float Q  = invU * invU - invL * invL;
        float Qp = -2.0f * invU * invU * invU + 2.0f * Lp * invL * invL * invL;
        float dC = 0.5f * ((Lp * invL - invU) / dd - logf(L * invU) / (dd * dd));
        float extra = (rho_t < sr - dd) ? 2.0f * Lp * invL * invL : 0.0f;
        float Ip = 0.5f * (dA + Pp * Q + P * Qp + dC + extra);
        float g = d_gd[e] + gst * Ip;
        float c = g / dd;
        float dx = pos[3 * s] - px, dy = pos[3 * s + 1] - py, dz = pos[3 * s + 2] - pz;
        atomicAdd(&d_gpos[3 * s],     c * dx);
        atomicAdd(&d_gpos[3 * s + 1], c * dy);
        atomicAdd(&d_gpos[3 * s + 2], c * dz);
        fx -= c * dx; fy -= c * dy; fz -= c * dz;
    }
    for (int o = 16; o; o >>= 1) {
        fx += __shfl_down_sync(0xffffffffu, fx, o);
        fy += __shfl_down_sync(0xffffffffu, fy, o);
        fz += __shfl_down_sync(0xffffffffu, fz, o);
    }
    if (lane == 0) {
        atomicAdd(&d_gpos[3 * t],     fx);
        atomicAdd(&d_gpos[3 * t + 1], fy);
        atomicAdd(&d_gpos[3 * t + 2], fz);
    }
}

// ---------------- outputs: block per molecule, in-block energy reduction ----------------
__global__ void k_out(float* out) {
    int m = blockIdx.x, t = threadIdx.x;
    int i = m * 256 + t;
    __shared__ float red[256];
    out[NM + 3 * i]     = -d_gpos[3 * i];
    out[NM + 3 * i + 1] = -d_gpos[3 * i + 1];
    out[NM + 3 * i + 2] = -d_gpos[3 * i + 2];
    red[t] = d_atomE[i];
    __syncthreads();
    for (int st = 128; st > 0; st >>= 1) {
        if (t < st) red[t] += red[t + st];
        __syncthreads();
    }
    if (t == 0) out[m] = red[0];
}

extern "C" void kernel_launch(void* const* d_in, const int* in_sizes, int n_in,
                              void* d_out, int out_size) {
    const float* pos  = (const float*)d_in[0];
    const float* ls   = (const float*)d_in[1];
    const float* le   = (const float*)d_in[2];
    const float* gp   = (const float*)d_in[3];
    const float* stw1 = (const float*)d_in[4];
    const float* stb1 = (const float*)d_in[5];
    const float* stw2 = (const float*)d_in[6];
    const float* stb2 = (const float*)d_in[7];
    const float* elw1 = (const float*)d_in[8];
    const float* elb1 = (const float*)d_in[9];
    const float* elw2 = (const float*)d_in[10];
    const float* elb2 = (const float*)d_in[11];
    const float* i1w1 = (const float*)d_in[12];
    const float* i1b1 = (const float*)d_in[13];
    const float* i1w2 = (const float*)d_in[14];
    const float* i1b2 = (const float*)d_in[15];
    const float* i2w1 = (const float*)d_in[16];
    const float* i2b1 = (const float*)d_in[17];
    const float* i2w2 = (const float*)d_in[18];
    const float* i2b2 = (const float*)d_in[19];
    const int*   ei   = (const int*)d_in[21];
    const int*   gei  = (const int*)d_in[22];
    float* out = (float*)d_out;

    int Egb  = in_sizes[21] / 2;
    int Egnn = in_sizes[22] / 2;
    const int* gbsrc = ei;
    const int* gbdst = ei + Egb;
    const int* gsrc  = gei;
    const int* gdst  = gei + Egnn;

    long setup_total = (long)NM + NA * 3 + 3 * HIDN * HIDN + Egb + Egnn;
    k_setup<<<(int)((setup_total + 255) / 256), 256>>>(ls, le, stw1, stb1, stw2, stb2,
                                                       elw1, elb1, elw2, elb2,
                                                       i1w2, i2w1, gbdst, Egb, gdst, Egnn);
    k_gb1<<<(NA * 32 + 255) / 256, 256>>>(pos, gp, gbsrc);
    k_born<<<(NA + 255) / 256, 256>>>(gp);
    k_pr<<<(NA * HIDN + 255) / 256, 256>>>(i1w1);
    k_l1fwd<<<NA / 4, HIDN>>>(gsrc, i1b1, i1w2, i1b2, i2w1);
    k_l2fwd<<<NA, HIDN>>>(gsrc, i2b1, i2w2, i2b2);
    k_post<<<(NA + 255) / 256, 256>>>(gp);
    k_pair<<<(NA * 32 + 255) / 256, 256>>>(gp, gbsrc);
    k_gO<<<(NA + 255) / 256, 256>>>(gp);
    k_bwd<<<NA / 2, HIDN>>>(gsrc, i2b1, i2w2);
    k_l1bwd<<<NA, HIDN>>>(gsrc, i1b1, i1w1);
    k_gbbwd<<<(NA * 32 + 255) / 256, 256>>>(pos, gp, gbsrc);
    k_out<<<NM, 256>>>(out);
}